// round 15
// baseline (speedup 1.0000x reference)
#include <cuda_runtime.h>
#include <math.h>

#define S 8192
#define D 2048
#define WSTRIDE 4096           // W row stride (2*D)
#define NCTA_REC 128
#define ROWS_PER_CTA 16        // D / NCTA_REC
#define NCHUNK 64
#define CHUNK 128              // S / NCHUNK
#define REC_THREADS 512

typedef unsigned long long ull;

// ---- scratch (no runtime allocation allowed) ----
__device__ float g_hc[(size_t)S * D];        // cummax result
__device__ float g_cp[(size_t)S * D];        // ctx_proj result
__device__ float g_chunkmax[NCHUNK * D];     // per-chunk column maxes
__device__ __align__(16) int g_flagv[NCTA_REC];  // per-CTA step counters

#define NEG_INF __int_as_float(0xff800000)

// ---- packed f32x2 helpers ----
__device__ __forceinline__ ull ffma2(ull a, ull b, ull c) {
    ull d;
    asm("fma.rn.f32x2 %0, %1, %2, %3;" : "=l"(d) : "l"(a), "l"(b), "l"(c));
    return d;
}
__device__ __forceinline__ ull pack2(unsigned int lo, unsigned int hi) {
    ull v;
    asm("mov.b64 %0, {%1, %2};" : "=l"(v) : "r"(lo), "r"(hi));
    return v;
}
__device__ __forceinline__ ull pack2f(float x, float y) {
    ull v;
    asm("mov.b64 %0, {%1, %2};" : "=l"(v) : "f"(x), "f"(y));
    return v;
}
__device__ __forceinline__ ull dup2f(float x) {
    ull v;
    asm("mov.b64 %0, {%1, %1};" : "=l"(v) : "f"(x));
    return v;
}
__device__ __forceinline__ float2 unpack2(ull v) {
    float2 r;
    asm("mov.b64 {%0, %1}, %2;" : "=f"(r.x), "=f"(r.y) : "l"(v));
    return r;
}

// ---- fence-free acquire/release primitives (NO atomics) ----
// One v4 acquire = ONE round trip covering 4 flags (vs 4 chained RTs).
__device__ __forceinline__ int4 ld_acquire_gpu_v4(const int* p) {
    int4 f;
    asm volatile("ld.acquire.gpu.global.v4.s32 {%0,%1,%2,%3}, [%4];"
                 : "=r"(f.x), "=r"(f.y), "=r"(f.z), "=r"(f.w)
                 : "l"(p) : "memory");
    return f;
}
__device__ __forceinline__ void st_release_gpu(int* p, int v) {
    asm volatile("st.release.gpu.global.s32 [%0], %1;" :: "l"(p), "r"(v) : "memory");
}

// ============================================================
// K1: cummax phase A (per-chunk column max) + flag reset.
// ============================================================
__global__ void cummax_chunk_kernel(const float* __restrict__ ce) {
    int tid = threadIdx.x;
    if (blockIdx.x == 0 && blockIdx.y == 0 && tid < NCTA_REC)
        g_flagv[tid] = 0;
    int col = blockIdx.x * blockDim.x + tid;
    int chunk = blockIdx.y;
    const float* p = ce + (size_t)chunk * CHUNK * D + col;
    float m = NEG_INF;
#pragma unroll 8
    for (int r = 0; r < CHUNK; r++) {
        m = fmaxf(m, p[(size_t)r * D]);
    }
    g_chunkmax[chunk * D + col] = m;
}

// ============================================================
// K2: cummax finish — rebuild exclusive chunk prefix (L2-hot),
// then inclusive-scan own chunk into g_hc.
// ============================================================
__global__ void cummax_finish_kernel(const float* __restrict__ ce) {
    int col = blockIdx.x * blockDim.x + threadIdx.x;
    int chunk = blockIdx.y;
    float m = NEG_INF;
#pragma unroll 8
    for (int ch = 0; ch < chunk; ch++)
        m = fmaxf(m, g_chunkmax[ch * D + col]);
    const float* p = ce + (size_t)chunk * CHUNK * D + col;
    float*       q = g_hc + (size_t)chunk * CHUNK * D + col;
#pragma unroll 8
    for (int r = 0; r < CHUNK; r++) {
        m = fmaxf(m, p[(size_t)r * D]);
        q[(size_t)r * D] = m;
    }
}

// ============================================================
// K3: GEMM: g_cp[t][i] = sum_j ce[t][j] * W[i][D + j] + b[i]
// f32x2 packed FFMA.
// ============================================================
#define GT 128
#define GI 128
#define GK 8
#define GPAD 4

__global__ __launch_bounds__(256) void gemm_ctx_kernel(
    const float* __restrict__ A,
    const float* __restrict__ W,
    const float* __restrict__ bias)
{
    __shared__ float As[GK][GT + GPAD];
    __shared__ float Bs[GK][GI + GPAD];

    int tid = threadIdx.x;
    int tx = tid & 15;
    int ty = tid >> 4;
    int i0 = blockIdx.x * GI;
    int t0 = blockIdx.y * GT;

    int lr = tid >> 1;
    int lk = (tid & 1) * 4;

    const float* Ap = A + (size_t)(t0 + lr) * D + lk;
    const float* Bp = W + (size_t)(i0 + lr) * WSTRIDE + D + lk;

    ull acc[8][4];
#pragma unroll
    for (int m = 0; m < 8; m++)
#pragma unroll
        for (int n = 0; n < 4; n++) acc[m][n] = 0ULL;

    float4 ra = *(const float4*)Ap;
    float4 rb = *(const float4*)Bp;

    for (int kk = 0; kk < D; kk += GK) {
        As[lk + 0][lr] = ra.x; As[lk + 1][lr] = ra.y;
        As[lk + 2][lr] = ra.z; As[lk + 3][lr] = ra.w;
        Bs[lk + 0][lr] = rb.x; Bs[lk + 1][lr] = rb.y;
        Bs[lk + 2][lr] = rb.z; Bs[lk + 3][lr] = rb.w;
        __syncthreads();

        if (kk + GK < D) {
            ra = *(const float4*)(Ap + kk + GK);
            rb = *(const float4*)(Bp + kk + GK);
        }

#pragma unroll
        for (int k = 0; k < GK; k++) {
            float4 a0 = *(const float4*)&As[k][ty * 8];
            float4 a1 = *(const float4*)&As[k][ty * 8 + 4];
            float4 b0 = *(const float4*)&Bs[k][tx * 8];
            float4 b1 = *(const float4*)&Bs[k][tx * 8 + 4];
            ull bp[4] = {pack2f(b0.x, b0.y), pack2f(b0.z, b0.w),
                         pack2f(b1.x, b1.y), pack2f(b1.z, b1.w)};
            ull ad[8] = {dup2f(a0.x), dup2f(a0.y), dup2f(a0.z), dup2f(a0.w),
                         dup2f(a1.x), dup2f(a1.y), dup2f(a1.z), dup2f(a1.w)};
#pragma unroll
            for (int m = 0; m < 8; m++)
#pragma unroll
                for (int n = 0; n < 4; n++)
                    acc[m][n] = ffma2(ad[m], bp[n], acc[m][n]);
        }
        __syncthreads();
    }

    float bv[8];
#pragma unroll
    for (int n = 0; n < 8; n++) bv[n] = bias[i0 + tx * 8 + n];

#pragma unroll
    for (int m = 0; m < 8; m++) {
        size_t row = (size_t)(t0 + ty * 8 + m) * D + i0 + tx * 8;
        float2 c0 = unpack2(acc[m][0]), c1 = unpack2(acc[m][1]);
        float2 c2 = unpack2(acc[m][2]), c3 = unpack2(acc[m][3]);
        float4 o0 = make_float4(c0.x + bv[0], c0.y + bv[1],
                                c1.x + bv[2], c1.y + bv[3]);
        float4 o1 = make_float4(c2.x + bv[4], c2.y + bv[5],
                                c3.x + bv[6], c3.y + bv[7]);
        *(float4*)&g_cp[row]     = o0;
        *(float4*)&g_cp[row + 4] = o1;
    }
}

// ============================================================
// K4: Recurrence v11 = v6 (best measured) with:
//  (a) ONE v4 acquire per poll iteration (1 RT, was 4 chained RTs)
//  (b) hc/cp pipelined a full step ahead in REGISTERS (no smem,
//      no STS before a barrier — the v10 mistake).
// 128 CTAs x 512 threads. c = tid & 127 owns 16 state cols,
// rgrp = tid >> 7 owns 4 rows. W slice in regs (f32x2).
// ============================================================
__global__ __launch_bounds__(REC_THREADS, 1) void recurrence_kernel(
    const float* __restrict__ W,
    float* out)
{
    __shared__ float s_red[2][16 * 4];   // [buf][row*4 + colpart]

    int tid  = threadIdx.x;
    int lane = tid & 31;
    int wrp  = tid >> 5;          // 0..15
    int c    = tid & 127;         // column segment
    int rgrp = tid >> 7;          // 0..3
    int wq   = wrp & 3;           // colpart within reduction
    int cta  = blockIdx.x;
    int i0   = cta * ROWS_PER_CTA;

    // ---- preload W slice as f32x2 pairs ----
    ull w2[4][8];
#pragma unroll
    for (int m = 0; m < 4; m++) {
        const float* wp = W + (size_t)(i0 + rgrp * 4 + m) * WSTRIDE + c * 16;
#pragma unroll
        for (int j = 0; j < 4; j++) {
            uint4 q = *(const uint4*)(wp + j * 4);
            w2[m][j * 2 + 0] = pack2(q.x, q.y);
            w2[m][j * 2 + 1] = pack2(q.z, q.w);
        }
    }

    const ull minus1 = pack2(__float_as_uint(-1.0f), __float_as_uint(-1.0f));

    // hc/cp register pipeline: values for step t live in hcv/cpv; the
    // loads for t+1 are issued at the top of step t (a full chain ahead).
    float hcv = 0.0f, cpv = 0.0f;
    if (tid < ROWS_PER_CTA) {
        hcv = __ldg(&g_hc[i0 + tid]);      // step 0
        cpv = __ldg(&g_cp[i0 + tid]);
    }

    for (int t = 0; t < S; t++) {
        // issue next step's hc/cp now; consumed at finalize of t+1
        float hcn = 0.0f, cpn = 0.0f;
        if (tid < ROWS_PER_CTA && t + 1 < S) {
            hcn = __ldg(&g_hc[(size_t)(t + 1) * D + i0 + tid]);
            cpn = __ldg(&g_cp[(size_t)(t + 1) * D + i0 + tid]);
        }

        // ---- wait until ALL 128 CTAs have published row t-1 ----
        // warp 0: lane l checks flags 4l..4l+3 with ONE v4 acquire
        if (t > 0 && wrp == 0) {
            const int* fp = g_flagv + lane * 4;
            for (;;) {
                int4 f = ld_acquire_gpu_v4(fp);
                int mn = min(min(f.x, f.y), min(f.z, f.w));
                if (__all_sync(0xFFFFFFFFu, mn >= t)) break;
            }
        }
        __syncthreads();   // join pollers + propagate acquire ordering

        // ---- obtain state segment (plain cached loads) ----
        ull sp[8];
        if (t == 0) {
#pragma unroll
            for (int j = 0; j < 8; j++) sp[j] = minus1;
        } else {
            const float* src = out + (size_t)(t - 1) * D + c * 16;
#pragma unroll
            for (int j = 0; j < 4; j++) {
                uint4 q = *(const uint4*)(src + j * 4);
                sp[j * 2 + 0] = pack2(q.x, q.y);
                sp[j * 2 + 1] = pack2(q.z, q.w);
            }
        }

        // ---- 4-row x 16-col partial matvec, packed f32x2 ----
        ull a0 = 0, a1 = 0, a2 = 0, a3 = 0;
#pragma unroll
        for (int j = 0; j < 8; j++) {
            a0 = ffma2(w2[0][j], sp[j], a0);
            a1 = ffma2(w2[1][j], sp[j], a1);
            a2 = ffma2(w2[2][j], sp[j], a2);
            a3 = ffma2(w2[3][j], sp[j], a3);
        }
        float2 f0 = unpack2(a0), f1 = unpack2(a1),
               f2 = unpack2(a2), f3 = unpack2(a3);
        float r0 = f0.x + f0.y;
        float r1 = f1.x + f1.y;
        float r2 = f2.x + f2.y;
        float r3 = f3.x + f3.y;

        // ---- warp shuffle reduction over 32 column segments ----
#pragma unroll
        for (int off = 16; off > 0; off >>= 1) {
            r0 += __shfl_xor_sync(0xFFFFFFFFu, r0, off);
            r1 += __shfl_xor_sync(0xFFFFFFFFu, r1, off);
            r2 += __shfl_xor_sync(0xFFFFFFFFu, r2, off);
            r3 += __shfl_xor_sync(0xFFFFFFFFu, r3, off);
        }
        int buf = t & 1;
        if (lane == 0) {
            int rb = rgrp * 4;
            s_red[buf][(rb + 0) * 4 + wq] = r0;
            s_red[buf][(rb + 1) * 4 + wq] = r1;
            s_red[buf][(rb + 2) * 4 + wq] = r2;
            s_red[buf][(rb + 3) * 4 + wq] = r3;
        }
        __syncthreads();

        // ---- finalize: 16 lanes of warp 0, then release-store the flag ----
        if (tid < ROWS_PER_CTA) {
            float4 v = *(const float4*)&s_red[buf][tid * 4];
            float s = (v.x + v.y) + (v.z + v.w);
            float x  = s + cpv;
            float g  = 1.0f / (1.0f + __expf(-x));
            float ns = hcv * g;
            __stcg(&out[(size_t)t * D + i0 + tid], ns);
            if (t == S - 1) __stcg(&out[(size_t)S * D + i0 + tid], ns);
            __syncwarp(0x0000FFFFu);   // all 16 row stores done
            if (tid == 0)
                st_release_gpu(&g_flagv[cta], t + 1);   // publish step t
        }
        hcv = hcn;   // rotate the hc/cp pipeline
        cpv = cpn;
        // s_red reuse at t+1 is safe: writes at t+1 occur after the t+1
        // top-of-loop __syncthreads, which follows every reader's access.
    }
}

// ============================================================
extern "C" void kernel_launch(void* const* d_in, const int* in_sizes, int n_in,
                              void* d_out, int out_size) {
    const float* ce = (const float*)d_in[0];   // (S, D)
    const float* W  = (const float*)d_in[1];   // (D, 2D)
    const float* b  = (const float*)d_in[2];   // (D,)
    float* out = (float*)d_out;                // (S*D + D) floats

    dim3 cgrid(D / 256, NCHUNK);
    cummax_chunk_kernel<<<cgrid, 256>>>(ce);    // launch 1 (+ flag reset)
    cummax_finish_kernel<<<cgrid, 256>>>(ce);   // launch 2

    dim3 ggrid(D / GI, S / GT);
    gemm_ctx_kernel<<<ggrid, 256>>>(ce, W, b);  // launch 3

    recurrence_kernel<<<NCTA_REC, REC_THREADS>>>(W, out);  // launch 4
}

// round 17
// speedup vs baseline: 1.3174x; 1.3174x over previous
#include <cuda_runtime.h>
#include <math.h>

#define S 8192
#define D 2048
#define WSTRIDE 4096           // W row stride (2*D)
#define NCTA_REC 128
#define ROWS_PER_CTA 16        // D / NCTA_REC
#define REC_THREADS 512
#define LA 2                   // ce lookahead (steps)
#define CE_RING 4              // ce smem ring slots
#define WCSTRIDE 2052          // padded W_ctx smem row stride (floats)
#define CPSTRIDE 36            // padded cp-partial row stride (floats)

typedef unsigned long long ull;
typedef unsigned int uint;

// ---- the only global scratch left ----
__device__ __align__(16) int g_flagv[NCTA_REC];  // per-CTA step counters

#define NEG_INF __int_as_float(0xff800000)

// ---- smem layout (bytes) ----
#define SM_WC    0                         // 16 x 2052 floats = 131328
#define SM_CE    131328                    // 4 x 2048 floats  = 32768
#define SM_RED   164096                    // 2 x 64 floats    = 512
#define SM_CPP   164608                    // 16 x 36 floats   = 2304
#define SM_TOTAL 166912

// ---- packed f32x2 helpers ----
__device__ __forceinline__ ull ffma2(ull a, ull b, ull c) {
    ull d;
    asm("fma.rn.f32x2 %0, %1, %2, %3;" : "=l"(d) : "l"(a), "l"(b), "l"(c));
    return d;
}
__device__ __forceinline__ ull pack2(uint lo, uint hi) {
    ull v;
    asm("mov.b64 %0, {%1, %2};" : "=l"(v) : "r"(lo), "r"(hi));
    return v;
}
__device__ __forceinline__ float2 unpack2(ull v) {
    float2 r;
    asm("mov.b64 {%0, %1}, %2;" : "=f"(r.x), "=f"(r.y) : "l"(v));
    return r;
}

// ---- fence-free acquire/release primitives (v6, best measured) ----
__device__ __forceinline__ int ld_acquire_gpu(const int* p) {
    int v;
    asm volatile("ld.acquire.gpu.global.s32 %0, [%1];" : "=r"(v) : "l"(p) : "memory");
    return v;
}
__device__ __forceinline__ void st_release_gpu(int* p, int v) {
    asm volatile("st.release.gpu.global.s32 [%0], %1;" :: "l"(p), "r"(v) : "memory");
}

// ---- cp.async ----
__device__ __forceinline__ void cp_async16(uint sa, const void* g) {
    asm volatile("cp.async.cg.shared.global [%0], [%1], 16;" :: "r"(sa), "l"(g));
}
#define CP_COMMIT() asm volatile("cp.async.commit_group;" ::: "memory")
#define CP_WAIT1()  asm volatile("cp.async.wait_group 1;" ::: "memory")

// ============================================================
// flag reset (graph replays must start from zeroed counters)
// ============================================================
__global__ void zero_flags_kernel() {
    if (threadIdx.x < NCTA_REC) g_flagv[threadIdx.x] = 0;
}

// ============================================================
// cp partials for one step: thread k -> row r=k&15, cols q*64..+64.
// Wc from smem (bank-safe stride 2052), ce broadcast from smem ring.
// ============================================================
__device__ __forceinline__ void compute_cpp(const float* s_wc, const float* ce_row,
                                            float* s_cpp, int tid) {
    int r = tid & 15, q = tid >> 4;
    const float* wr = s_wc + r * WCSTRIDE + q * 64;
    const float* cr = ce_row + q * 64;
    float acc = 0.0f;
#pragma unroll
    for (int j = 0; j < 64; j += 4) {
        float4 wv = *(const float4*)(wr + j);
        float4 cv = *(const float4*)(cr + j);
        acc = fmaf(wv.x, cv.x, acc); acc = fmaf(wv.y, cv.y, acc);
        acc = fmaf(wv.z, cv.z, acc); acc = fmaf(wv.w, cv.w, acc);
    }
    s_cpp[r * CPSTRIDE + q] = acc;
}

// ============================================================
// Fused persistent kernel: cummax + ctx_proj + recurrence.
// 128 CTAs x 512 threads. Critical path (poll/state/reduce/publish)
// is v6 verbatim. cp computed in the post-release shadow from a
// smem W_ctx slice + cp.async-streamed ce rows; hc is a running max
// in the finalize lanes. No g_hc/g_cp arrays at all.
// ============================================================
__global__ __launch_bounds__(REC_THREADS, 1) void fused_kernel(
    const float* __restrict__ W,
    const float* __restrict__ ce,
    const float* __restrict__ bias,
    float* out)
{
    extern __shared__ char smem[];
    float* s_wc  = (float*)(smem + SM_WC);
    float* s_ce  = (float*)(smem + SM_CE);
    float* s_red = (float*)(smem + SM_RED);
    float* s_cpp = (float*)(smem + SM_CPP);

    int tid  = threadIdx.x;
    int lane = tid & 31;
    int wrp  = tid >> 5;
    int c    = tid & 127;         // state column segment
    int rgrp = tid >> 7;          // 0..3
    int wq   = wrp & 3;
    int cta  = blockIdx.x;
    int i0   = cta * ROWS_PER_CTA;

    // ---- W_state slice in regs (v6) ----
    ull w2[4][8];
#pragma unroll
    for (int m = 0; m < 4; m++) {
        const float* wp = W + (size_t)(i0 + rgrp * 4 + m) * WSTRIDE + c * 16;
#pragma unroll
        for (int j = 0; j < 4; j++) {
            uint4 q = *(const uint4*)(wp + j * 4);
            w2[m][j * 2 + 0] = pack2(q.x, q.y);
            w2[m][j * 2 + 1] = pack2(q.z, q.w);
        }
    }

    // ---- prologue: W_ctx slice (16 x 2048) -> smem ----
#pragma unroll 4
    for (int r = 0; r < ROWS_PER_CTA; r++) {
        float4 v = *(const float4*)(W + (size_t)(i0 + r) * WSTRIDE + D + tid * 4);
        *(float4*)&s_wc[r * WCSTRIDE + tid * 4] = v;
    }
    // ---- prologue: ce[0], ce[1] via cp.async (one 16B chunk/thread) ----
    {
        uint sa0 = (uint)__cvta_generic_to_shared(&s_ce[0 * D + tid * 4]);
        uint sa1 = (uint)__cvta_generic_to_shared(&s_ce[1 * D + tid * 4]);
        cp_async16(sa0, ce + tid * 4);            CP_COMMIT();
        cp_async16(sa1, ce + D + tid * 4);        CP_COMMIT();
    }
    CP_WAIT1();          // ce[0] complete (<=1 group in flight)
    __syncthreads();     // Wc + ce[0] visible to all
    compute_cpp(s_wc, s_ce, s_cpp, tid);   // cp partials for t=0

    const ull minus1 = pack2(__float_as_uint(-1.0f), __float_as_uint(-1.0f));
    float hc_run = NEG_INF;
    float bb = 0.0f;
    if (tid < ROWS_PER_CTA) bb = __ldg(&bias[i0 + tid]);

    for (int t = 0; t < S; t++) {
        // ---- wait until ALL 128 CTAs have published row t-1 (v6) ----
        if (t > 0 && wrp == 0) {
            const int* fp = g_flagv + lane;
            for (;;) {
                int f0 = ld_acquire_gpu(fp);
                int f1 = ld_acquire_gpu(fp + 32);
                int f2 = ld_acquire_gpu(fp + 64);
                int f3 = ld_acquire_gpu(fp + 96);
                int mn = min(min(f0, f1), min(f2, f3));
                if (__all_sync(0xFFFFFFFFu, mn >= t)) break;
            }
        }
        __syncthreads();   // join pollers + propagate acquire ordering
                           // (at t=0 also orders the prologue cpp writes)

        // ---- state segment (plain cached loads, v6) ----
        ull sp[8];
        if (t == 0) {
#pragma unroll
            for (int j = 0; j < 8; j++) sp[j] = minus1;
        } else {
            const float* src = out + (size_t)(t - 1) * D + c * 16;
#pragma unroll
            for (int j = 0; j < 4; j++) {
                uint4 q = *(const uint4*)(src + j * 4);
                sp[j * 2 + 0] = pack2(q.x, q.y);
                sp[j * 2 + 1] = pack2(q.z, q.w);
            }
        }

        // ---- 4-row x 16-col state matvec, packed f32x2 (v6) ----
        ull a0 = 0, a1 = 0, a2 = 0, a3 = 0;
#pragma unroll
        for (int j = 0; j < 8; j++) {
            a0 = ffma2(w2[0][j], sp[j], a0);
            a1 = ffma2(w2[1][j], sp[j], a1);
            a2 = ffma2(w2[2][j], sp[j], a2);
            a3 = ffma2(w2[3][j], sp[j], a3);
        }
        float2 f0 = unpack2(a0), f1 = unpack2(a1),
               f2 = unpack2(a2), f3 = unpack2(a3);
        float r0 = f0.x + f0.y;
        float r1 = f1.x + f1.y;
        float r2 = f2.x + f2.y;
        float r3 = f3.x + f3.y;

#pragma unroll
        for (int off = 16; off > 0; off >>= 1) {
            r0 += __shfl_xor_sync(0xFFFFFFFFu, r0, off);
            r1 += __shfl_xor_sync(0xFFFFFFFFu, r1, off);
            r2 += __shfl_xor_sync(0xFFFFFFFFu, r2, off);
            r3 += __shfl_xor_sync(0xFFFFFFFFu, r3, off);
        }
        int buf = t & 1;
        if (lane == 0) {
            int rb = rgrp * 4;
            s_red[buf * 64 + (rb + 0) * 4 + wq] = r0;
            s_red[buf * 64 + (rb + 1) * 4 + wq] = r1;
            s_red[buf * 64 + (rb + 2) * 4 + wq] = r2;
            s_red[buf * 64 + (rb + 3) * 4 + wq] = r3;
        }
        __syncthreads();

        // ---- finalize: cp sum + running hc + sigmoid + publish ----
        if (tid < ROWS_PER_CTA) {
            // cp[t][i0+tid]: 32 partials (8 x LDS.128, 16B-aligned stride)
            const float* pp = &s_cpp[tid * CPSTRIDE];
            float cp = bb;
#pragma unroll
            for (int j = 0; j < 32; j += 4) {
                float4 v = *(const float4*)(pp + j);
                cp += (v.x + v.y) + (v.z + v.w);
            }
            // hc: running column max from the smem ce row
            hc_run = fmaxf(hc_run, s_ce[(t & (CE_RING - 1)) * D + i0 + tid]);

            float4 v = *(const float4*)&s_red[buf * 64 + tid * 4];
            float s  = (v.x + v.y) + (v.z + v.w);
            float x  = s + cp;
            float g  = 1.0f / (1.0f + __expf(-x));
            float ns = hc_run * g;
            __stcg(&out[(size_t)t * D + i0 + tid], ns);
            if (t == S - 1) __stcg(&out[(size_t)S * D + i0 + tid], ns);
            __syncwarp(0x0000FFFFu);
            if (tid == 0)
                st_release_gpu(&g_flagv[cta], t + 1);   // publish step t
        }

        // ---- post-release shadow: stream ce, build next cp partials ----
        if (t + LA < S) {
            uint sa = (uint)__cvta_generic_to_shared(
                &s_ce[((t + LA) & (CE_RING - 1)) * D + tid * 4]);
            cp_async16(sa, ce + (size_t)(t + LA) * D + tid * 4);
        }
        CP_COMMIT();       // always commit (possibly empty) to keep groups aligned
        CP_WAIT1();        // ce[t+1] complete
        __syncthreads();   // ce[t+1] visible; orders finalize's s_cpp reads
                           // (pre-barrier) before the writes below
        if (t + 1 < S)
            compute_cpp(s_wc, &s_ce[((t + 1) & (CE_RING - 1)) * D], s_cpp, tid);
        // ring safety: slot (t+LA)&3 written above was last read at
        // step t-2 (hc/cpp), separated by multiple barriers.
    }
}

// ============================================================
extern "C" void kernel_launch(void* const* d_in, const int* in_sizes, int n_in,
                              void* d_out, int out_size) {
    const float* ce = (const float*)d_in[0];   // (S, D)
    const float* W  = (const float*)d_in[1];   // (D, 2D)
    const float* b  = (const float*)d_in[2];   // (D,)
    float* out = (float*)d_out;                // (S*D + D) floats

    cudaFuncSetAttribute(fused_kernel,
                         cudaFuncAttributeMaxDynamicSharedMemorySize, SM_TOTAL);

    zero_flags_kernel<<<1, 128>>>();
    fused_kernel<<<NCTA_REC, REC_THREADS, SM_TOTAL>>>(W, ce, b, out);
}